// round 12
// baseline (speedup 1.0000x reference)
#include <cuda_runtime.h>
#include <cuda_bf16.h>

#define BATCH 65536
#define EMBED 128
#define HIST 5
#define NEG 2

__device__ __forceinline__ float warp_sum(float v) {
    #pragma unroll
    for (int o = 16; o; o >>= 1) v += __shfl_xor_sync(0xFFFFFFFFu, v, o);
    return v;
}

// L2-only load of a float4 (no L1 allocate): emb rows have no L1 reuse.
__device__ __forceinline__ float4 ldcg4(const float4* p) {
    return __ldcg(p);
}

__device__ __forceinline__ float sq4(float4 a, float4 b) {
    float dx = a.x - b.x, dy = a.y - b.y, dz = a.z - b.z, dw = a.w - b.w;
    return dx*dx + dy*dy + dz*dz + dw*dw;
}

__device__ __forceinline__ float log_sigmoid(float x) {
    // stable: min(x,0) - log1p(exp(-|x|))
    return fminf(x, 0.0f) - log1pf(__expf(-fabsf(x)));
}

__global__ __launch_bounds__(128, 10)
void htne_kernel(const int* __restrict__ xs,
                 const int* __restrict__ ys,
                 const float* __restrict__ e_times,
                 const int* __restrict__ hs,
                 const float* __restrict__ h_times,
                 const int* __restrict__ neg_node,
                 const float* __restrict__ h_times_mask,
                 const float* __restrict__ emb,
                 const float* __restrict__ delta_tab,
                 float* __restrict__ out)
{
    int warp = (blockIdx.x * blockDim.x + threadIdx.x) >> 5;
    int lane = threadIdx.x & 31;
    if (warp >= BATCH) return;

    const int b = warp;

    // ---- index + scalar loads (uniform per warp; broadcast via L1) ----
    const int xi = __ldg(xs + b);
    const int yi = __ldg(ys + b);
    int hi[HIST];
    #pragma unroll
    for (int j = 0; j < HIST; j++) hi[j] = __ldg(hs + b * HIST + j);
    int ni[NEG];
    #pragma unroll
    for (int k = 0; k < NEG; k++) ni[k] = __ldg(neg_node + b * NEG + k);

    // ---- issue all 9 row gathers up front (max MLP), L2-only ----
    const float4* __restrict__ emb4 = (const float4*)emb;
    const int row4 = EMBED / 4;        // 32 float4 per row
    const int c4 = lane;

    float4 xe = ldcg4(emb4 + (size_t)xi * row4 + c4);
    float4 ye = ldcg4(emb4 + (size_t)yi * row4 + c4);
    float4 he[HIST];
    #pragma unroll
    for (int j = 0; j < HIST; j++) he[j] = ldcg4(emb4 + (size_t)hi[j] * row4 + c4);
    float4 ne[NEG];
    #pragma unroll
    for (int k = 0; k < NEG; k++) ne[k] = ldcg4(emb4 + (size_t)ni[k] * row4 + c4);

    const float et    = __ldg(e_times + b);
    const float delta = __ldg(delta_tab + xi);
    float ht[HIST], hm[HIST];
    #pragma unroll
    for (int j = 0; j < HIST; j++) {
        ht[j] = __ldg(h_times + b * HIST + j);
        hm[j] = __ldg(h_times_mask + b * HIST + j);
    }

    // ---- per-lane squared-distance partials ----
    float p_mu_p = sq4(xe, ye);
    float alpha_p[HIST];
    #pragma unroll
    for (int j = 0; j < HIST; j++) alpha_p[j] = sq4(xe, he[j]);
    float n_mu_p[NEG];
    #pragma unroll
    for (int k = 0; k < NEG; k++) n_mu_p[k] = sq4(xe, ne[k]);
    float n_alpha_p[HIST][NEG];
    #pragma unroll
    for (int j = 0; j < HIST; j++)
        #pragma unroll
        for (int k = 0; k < NEG; k++) n_alpha_p[j][k] = sq4(he[j], ne[k]);

    // ---- primary reductions: 1 p_mu + 5 alpha ----
    float p_mu = -warp_sum(p_mu_p);
    float alpha[HIST];
    #pragma unroll
    for (int j = 0; j < HIST; j++) alpha[j] = -warp_sum(alpha_p[j]);

    // ---- softmax weights + decay (uniform across lanes) ----
    float amax = alpha[0];
    #pragma unroll
    for (int j = 1; j < HIST; j++) amax = fmaxf(amax, alpha[j]);
    float attn[HIST], esum = 0.0f;
    #pragma unroll
    for (int j = 0; j < HIST; j++) { attn[j] = __expf(alpha[j] - amax); esum += attn[j]; }
    float inv = 1.0f / esum;

    float p_lambda = p_mu;
    float w[HIST];  // attn * decay (uniform across lanes)
    #pragma unroll
    for (int j = 0; j < HIST; j++) {
        float d_time = fabsf(et - ht[j]);
        float decay = __expf(delta * d_time) * hm[j];
        w[j] = attn[j] * inv * decay;
        p_lambda += w[j] * alpha[j];
    }

    // ---- fused negative-path reductions: 2 total ----
    // n_lambda[k] = n_mu[k] + sum_j w_j * n_alpha[j][k]
    //            = -warp_sum( n_mu_p[k] + sum_j w_j * n_alpha_p[j][k] )
    float n_lambda[NEG];
    #pragma unroll
    for (int k = 0; k < NEG; k++) {
        float t = n_mu_p[k];
        #pragma unroll
        for (int j = 0; j < HIST; j++) t += w[j] * n_alpha_p[j][k];
        n_lambda[k] = -warp_sum(t);
    }

    float loss = log_sigmoid(p_lambda);
    #pragma unroll
    for (int k = 0; k < NEG; k++) loss -= log_sigmoid(n_lambda[k]);

    if (lane == 0) out[b] = loss;
}

extern "C" void kernel_launch(void* const* d_in, const int* in_sizes, int n_in,
                              void* d_out, int out_size)
{
    const int*   xs        = (const int*)  d_in[0];
    const int*   ys        = (const int*)  d_in[1];
    const float* e_times   = (const float*)d_in[2];
    const int*   hs        = (const int*)  d_in[3];
    const float* h_times   = (const float*)d_in[4];
    const int*   neg_node  = (const int*)  d_in[5];
    const float* h_mask    = (const float*)d_in[6];
    const float* emb       = (const float*)d_in[7];
    const float* delta_tab = (const float*)d_in[8];
    float* out = (float*)d_out;

    const int threads = 128;                   // 4 warps/block
    const int blocks = (BATCH * 32) / threads; // 16384
    htne_kernel<<<blocks, threads>>>(xs, ys, e_times, hs, h_times, neg_node,
                                     h_mask, emb, delta_tab, out);
}

// round 13
// speedup vs baseline: 1.0484x; 1.0484x over previous
#include <cuda_runtime.h>
#include <cuda_bf16.h>

#define BATCH 65536
#define EMBED 128
#define HIST 5
#define NEG 2

__device__ __forceinline__ float warp_sum(float v) {
    #pragma unroll
    for (int o = 16; o; o >>= 1) v += __shfl_xor_sync(0xFFFFFFFFu, v, o);
    return v;
}

__device__ __forceinline__ float sq4(float4 a, float4 b) {
    float dx = a.x - b.x, dy = a.y - b.y, dz = a.z - b.z, dw = a.w - b.w;
    return dx*dx + dy*dy + dz*dz + dw*dw;
}

__device__ __forceinline__ float log_sigmoid(float x) {
    // stable: min(x,0) - log1p(exp(-|x|))
    return fminf(x, 0.0f) - log1pf(__expf(-fabsf(x)));
}

__global__ __launch_bounds__(128, 10)
void htne_kernel(const int* __restrict__ xs,
                 const int* __restrict__ ys,
                 const float* __restrict__ e_times,
                 const int* __restrict__ hs,
                 const float* __restrict__ h_times,
                 const int* __restrict__ neg_node,
                 const float* __restrict__ h_times_mask,
                 const float* __restrict__ emb,
                 const float* __restrict__ delta_tab,
                 float* __restrict__ out)
{
    int warp = (blockIdx.x * blockDim.x + threadIdx.x) >> 5;
    int lane = threadIdx.x & 31;
    if (warp >= BATCH) return;

    const int b = warp;

    // ---- index + scalar loads (uniform per warp; broadcast via L1) ----
    const int xi = __ldg(xs + b);
    const int yi = __ldg(ys + b);
    int hi[HIST];
    #pragma unroll
    for (int j = 0; j < HIST; j++) hi[j] = __ldg(hs + b * HIST + j);
    int ni[NEG];
    #pragma unroll
    for (int k = 0; k < NEG; k++) ni[k] = __ldg(neg_node + b * NEG + k);

    // ---- issue all 9 row gathers up front (max MLP) ----
    const float4* __restrict__ emb4 = (const float4*)emb;
    const int row4 = EMBED / 4;        // 32 float4 per row
    const int c4 = lane;

    float4 xe = __ldg(emb4 + (size_t)xi * row4 + c4);
    float4 ye = __ldg(emb4 + (size_t)yi * row4 + c4);
    float4 he[HIST];
    #pragma unroll
    for (int j = 0; j < HIST; j++) he[j] = __ldg(emb4 + (size_t)hi[j] * row4 + c4);
    float4 ne[NEG];
    #pragma unroll
    for (int k = 0; k < NEG; k++) ne[k] = __ldg(emb4 + (size_t)ni[k] * row4 + c4);

    const float et    = __ldg(e_times + b);
    const float delta = __ldg(delta_tab + xi);
    float ht[HIST], hm[HIST];
    #pragma unroll
    for (int j = 0; j < HIST; j++) {
        ht[j] = __ldg(h_times + b * HIST + j);
        hm[j] = __ldg(h_times_mask + b * HIST + j);
    }

    // ---- per-lane squared-distance partials ----
    float p_mu_p = sq4(xe, ye);
    float alpha_p[HIST];
    #pragma unroll
    for (int j = 0; j < HIST; j++) alpha_p[j] = sq4(xe, he[j]);
    float n_mu_p[NEG];
    #pragma unroll
    for (int k = 0; k < NEG; k++) n_mu_p[k] = sq4(xe, ne[k]);
    float n_alpha_p[HIST][NEG];
    #pragma unroll
    for (int j = 0; j < HIST; j++)
        #pragma unroll
        for (int k = 0; k < NEG; k++) n_alpha_p[j][k] = sq4(he[j], ne[k]);

    // ---- primary reductions: 1 p_mu + 5 alpha ----
    float p_mu = -warp_sum(p_mu_p);
    float alpha[HIST];
    #pragma unroll
    for (int j = 0; j < HIST; j++) alpha[j] = -warp_sum(alpha_p[j]);

    // ---- softmax weights + decay (uniform across lanes) ----
    float amax = alpha[0];
    #pragma unroll
    for (int j = 1; j < HIST; j++) amax = fmaxf(amax, alpha[j]);
    float attn[HIST], esum = 0.0f;
    #pragma unroll
    for (int j = 0; j < HIST; j++) { attn[j] = __expf(alpha[j] - amax); esum += attn[j]; }
    float inv = 1.0f / esum;

    float p_lambda = p_mu;
    float w[HIST];  // attn * decay (uniform across lanes)
    #pragma unroll
    for (int j = 0; j < HIST; j++) {
        float d_time = fabsf(et - ht[j]);
        float decay = __expf(delta * d_time) * hm[j];
        w[j] = attn[j] * inv * decay;
        p_lambda += w[j] * alpha[j];
    }

    // ---- fused negative-path reductions: 2 total ----
    // n_lambda[k] = n_mu[k] + sum_j w_j * n_alpha[j][k]
    //            = -warp_sum( n_mu_p[k] + sum_j w_j * n_alpha_p[j][k] )
    float n_lambda[NEG];
    #pragma unroll
    for (int k = 0; k < NEG; k++) {
        float t = n_mu_p[k];
        #pragma unroll
        for (int j = 0; j < HIST; j++) t += w[j] * n_alpha_p[j][k];
        n_lambda[k] = -warp_sum(t);
    }

    float loss = log_sigmoid(p_lambda);
    #pragma unroll
    for (int k = 0; k < NEG; k++) loss -= log_sigmoid(n_lambda[k]);

    if (lane == 0) out[b] = loss;
}

extern "C" void kernel_launch(void* const* d_in, const int* in_sizes, int n_in,
                              void* d_out, int out_size)
{
    const int*   xs        = (const int*)  d_in[0];
    const int*   ys        = (const int*)  d_in[1];
    const float* e_times   = (const float*)d_in[2];
    const int*   hs        = (const int*)  d_in[3];
    const float* h_times   = (const float*)d_in[4];
    const int*   neg_node  = (const int*)  d_in[5];
    const float* h_mask    = (const float*)d_in[6];
    const float* emb       = (const float*)d_in[7];
    const float* delta_tab = (const float*)d_in[8];
    float* out = (float*)d_out;

    const int threads = 128;                   // 4 warps/block
    const int blocks = (BATCH * 32) / threads; // 16384
    htne_kernel<<<blocks, threads>>>(xs, ys, e_times, hs, h_times, neg_node,
                                     h_mask, emb, delta_tab, out);
}